// round 4
// baseline (speedup 1.0000x reference)
#include <cuda_runtime.h>
#include <cuda_bf16.h>
#include <cstdint>
#include <cstddef>

// ============================================================================
// out = clip(x @ sign(W1)^T + b1, -1, 1) @ W2^T + b2
// sm_100 (no tcgen05): int8 IMMA m16n8k32 path.
//   x -> fixed-point hi/lo int8 (hi = rint(16x), lo = rint(256*(16x-hi)))
//   sign(W1) exact in s8. Two s32 GEMM accumulations, combined in f32 epilogue.
//   Layer 2 fused in epilogue (f32 scalar), deterministic partial reduce.
// ============================================================================

#define BATCH   8192
#define IN_F    784
#define HID     4096
#define OUT_F   10
#define KP      832            // 784 padded to 13*64
#define NCHUNK  13
#define TILE_M  128
#define TILE_N  256
#define NT_M    (BATCH / TILE_M)   // 64
#define NT_N    (HID / TILE_N)     // 16
#define NSTG    4

// ---------------- device scratch ---------------------------------------------
#define AHI_OFF 0
#define ALO_OFF (BATCH * KP)               // 6,815,744
#define WB_OFF  (2 * BATCH * KP)           // 13,631,488
__device__ int8_t g_data[2 * BATCH * KP + HID * KP];
__device__ float  g_part[(size_t)NT_N * BATCH * 16];

// ---------------- SMEM layout (bytes) ----------------------------------------
#define SM_B1     0                         // 256 f32 = 1KB
#define SM_W2     1024                      // 10*256 f32 = 10KB
#define SM_STG    12288                     // 4 stages x 32KB
#define STG_BYTES 32768
#define ST_AHI    0                         // 128 rows x 64B = 8KB
#define ST_ALO    8192
#define ST_B      16384                     // 256 rows x 64B = 16KB
#define SM_H      SM_STG                    // h tile overlaps stage region
#define H_STRIDE  258
#define SMEM_TOTAL (SM_STG + TILE_M * H_STRIDE * 4)   // 144,384 (stages end 143,360)
static_assert(SM_STG + NSTG * STG_BYTES <= SMEM_TOTAL, "stages inside smem");
static_assert(SMEM_TOTAL <= 227 * 1024, "smem budget");

// ---------------- PTX helpers -------------------------------------------------
__device__ __forceinline__ uint32_t smem_u32(const void* p) {
    uint32_t a;
    asm("{ .reg .u64 t; cvta.to.shared.u64 t, %1; cvt.u32.u64 %0, t; }"
        : "=r"(a) : "l"(p));
    return a;
}
__device__ __forceinline__ void cp_async16(uint32_t sm, const void* gp) {
    asm volatile("cp.async.cg.shared.global [%0], [%1], 16;" :: "r"(sm), "l"(gp));
}
__device__ __forceinline__ void ldsm_x4(uint32_t& r0, uint32_t& r1,
                                        uint32_t& r2, uint32_t& r3, uint32_t a) {
    asm volatile("ldmatrix.sync.aligned.m8n8.x4.shared.b16 {%0,%1,%2,%3}, [%4];"
                 : "=r"(r0), "=r"(r1), "=r"(r2), "=r"(r3) : "r"(a));
}
__device__ __forceinline__ void imma(int& c0, int& c1, int& c2, int& c3,
                                     uint32_t a0, uint32_t a1, uint32_t a2,
                                     uint32_t a3, uint32_t b0, uint32_t b1) {
    asm volatile(
        "mma.sync.aligned.m16n8k32.row.col.s32.s8.s8.s32 "
        "{%0,%1,%2,%3}, {%4,%5,%6,%7}, {%8,%9}, {%0,%1,%2,%3};"
        : "+r"(c0), "+r"(c1), "+r"(c2), "+r"(c3)
        : "r"(a0), "r"(a1), "r"(a2), "r"(a3), "r"(b0), "r"(b1));
}

// swizzled offset within a 64B-row tile: row*64 + ((seg ^ ((row>>1)&3))*16)
__device__ __forceinline__ uint32_t swz64(int row, int seg) {
    return (uint32_t)(row * 64 + ((seg ^ ((row >> 1) & 3)) << 4));
}

// ---------------- prep kernels ------------------------------------------------
__global__ void prep_x(const float* __restrict__ x) {
    int idx = blockIdx.x * blockDim.x + threadIdx.x;
    if (idx >= BATCH * KP) return;
    int r = idx / KP, c = idx - r * KP;
    float v = (c < IN_F) ? x[r * IN_F + c] : 0.f;
    float sv = v * 16.f;
    float hf = rintf(sv);
    int   lo = (int)rintf((sv - hf) * 256.f);
    lo = lo > 127 ? 127 : lo;
    g_data[AHI_OFF + idx] = (int8_t)(int)hf;
    g_data[ALO_OFF + idx] = (int8_t)lo;
}

__global__ void prep_w(const float* __restrict__ W1) {
    int idx = blockIdx.x * blockDim.x + threadIdx.x;
    if (idx >= HID * KP) return;
    int r = idx / KP, c = idx - r * KP;
    int s = 0;
    if (c < IN_F) {
        float v = W1[r * IN_F + c];
        s = (v > 0.f) ? 1 : ((v < 0.f) ? -1 : 0);
    }
    g_data[WB_OFF + idx] = (int8_t)s;
}

__global__ void reduce_out(const float* __restrict__ b2, float* __restrict__ out) {
    int idx = blockIdx.x * blockDim.x + threadIdx.x;
    if (idx >= BATCH * OUT_F) return;
    int r = idx / OUT_F, o = idx - r * OUT_F;
    float acc = b2[o];
#pragma unroll
    for (int nt = 0; nt < NT_N; nt++)
        acc += g_part[((size_t)nt * BATCH + r) * 16 + o];
    out[idx] = acc;
}

// ---------------- main fused kernel -------------------------------------------
__global__ void __launch_bounds__(512, 1)
mlp_kernel(const float* __restrict__ b1, const float* __restrict__ W2) {
    extern __shared__ __align__(128) char smem[];
    const uint32_t sb = smem_u32(smem);
    const int tid  = threadIdx.x;
    const int lane = tid & 31, wid = tid >> 5;
    const int m0 = blockIdx.x * TILE_M;
    const int n0 = blockIdx.y * TILE_N;
    const int warpM = wid & 1;        // 2 along M (64 rows each)
    const int warpN = wid >> 1;       // 8 along N (32 cols each)

    // preload b1 slice + W2 slice (f32)
    if (tid < 256) ((float*)(smem + SM_B1))[tid] = b1[n0 + tid];
#pragma unroll
    for (int i = tid; i < 10 * 256; i += 512)
        ((float*)(smem + SM_W2))[i] = W2[(i >> 8) * HID + n0 + (i & 255)];

    // per-thread cp.async segments: 2048 segs of 16B per chunk, 4 per thread
    uint32_t goff[4], soff[4];
#pragma unroll
    for (int i = 0; i < 4; i++) {
        int idx = tid + i * 512;
        int r, seg; uint32_t gb, sbs;
        if (idx < 512)       { r = idx >> 2; seg = idx & 3;
                               gb = (uint32_t)(AHI_OFF + (m0 + r) * KP); sbs = ST_AHI; }
        else if (idx < 1024) { int li = idx - 512;  r = li >> 2; seg = li & 3;
                               gb = (uint32_t)(ALO_OFF + (m0 + r) * KP); sbs = ST_ALO; }
        else                 { int li = idx - 1024; r = li >> 2; seg = li & 3;
                               gb = (uint32_t)(WB_OFF + (n0 + r) * KP);  sbs = ST_B; }
        goff[i] = gb + (uint32_t)(seg * 16);
        soff[i] = sbs + swz64(r, seg);
    }
    const char* gB = (const char*)g_data;

    // prologue: fill stages 0..2 (chunks 0..2; 64B advance per chunk)
#pragma unroll
    for (int pc = 0; pc < 3; pc++) {
        uint32_t st = sb + SM_STG + pc * STG_BYTES;
#pragma unroll
        for (int i = 0; i < 4; i++)
            cp_async16(st + soff[i], gB + goff[i] + pc * 64);
        asm volatile("cp.async.commit_group;");
    }

    // ldmatrix per-thread invariants (int8 m16n8k32 fragments via b16 ldmatrix)
    const int lm  = lane >> 3;                     // matrix id 0..3
    const int rAo = ((lm & 1) << 3) + (lane & 7);  // A: row offset within 16
    const int sAh = lm >> 1;                       // A: 16B half within k32
    const int rBo = ((lm >> 1) << 3) + (lane & 7); // B: n-row offset within 16
    const int sBh = lm & 1;                        // B: 16B half within k32

    int chi[4][4][4], clo[4][4][4];
#pragma unroll
    for (int mf = 0; mf < 4; mf++)
#pragma unroll
        for (int nf = 0; nf < 4; nf++)
#pragma unroll
            for (int q = 0; q < 4; q++) { chi[mf][nf][q] = 0; clo[mf][nf][q] = 0; }

    int stg_i = 0;
#pragma unroll 1
    for (int ck = 0; ck < NCHUNK; ck++) {
        asm volatile("cp.async.wait_group 2;");
        __syncthreads();                      // everyone's chunk ck data visible
        const uint32_t stg = sb + SM_STG + stg_i * STG_BYTES;

#pragma unroll
        for (int ks = 0; ks < 2; ks++) {      // two k32 steps per 64-K chunk
            // B fragments: 2 ldsm_x4, each covers two n8 groups
            uint32_t b[4][2];
#pragma unroll
            for (int p = 0; p < 2; p++) {
                int nrow = warpN * 32 + p * 16 + rBo;
                uint32_t addr = stg + ST_B + swz64(nrow, ks * 2 + sBh);
                ldsm_x4(b[2 * p][0], b[2 * p][1], b[2 * p + 1][0], b[2 * p + 1][1],
                        addr);
            }
            uint32_t a[4][4];
            // hi pass
#pragma unroll
            for (int mf = 0; mf < 4; mf++) {
                int row = warpM * 64 + mf * 16 + rAo;
                uint32_t addr = stg + ST_AHI + swz64(row, ks * 2 + sAh);
                ldsm_x4(a[mf][0], a[mf][1], a[mf][2], a[mf][3], addr);
            }
#pragma unroll
            for (int mf = 0; mf < 4; mf++)
#pragma unroll
                for (int nf = 0; nf < 4; nf++)
                    imma(chi[mf][nf][0], chi[mf][nf][1], chi[mf][nf][2], chi[mf][nf][3],
                         a[mf][0], a[mf][1], a[mf][2], a[mf][3], b[nf][0], b[nf][1]);
            // lo pass (reuses B fragments)
#pragma unroll
            for (int mf = 0; mf < 4; mf++) {
                int row = warpM * 64 + mf * 16 + rAo;
                uint32_t addr = stg + ST_ALO + swz64(row, ks * 2 + sAh);
                ldsm_x4(a[mf][0], a[mf][1], a[mf][2], a[mf][3], addr);
            }
#pragma unroll
            for (int mf = 0; mf < 4; mf++)
#pragma unroll
                for (int nf = 0; nf < 4; nf++)
                    imma(clo[mf][nf][0], clo[mf][nf][1], clo[mf][nf][2], clo[mf][nf][3],
                         a[mf][0], a[mf][1], a[mf][2], a[mf][3], b[nf][0], b[nf][1]);
        }

        // prefetch chunk ck+3 into stage (ck+3)%4 (= stage read in iter ck-1,
        // safe after this iteration's barrier)
        if (ck + 3 < NCHUNK) {
            uint32_t pst = sb + SM_STG + ((ck + 3) & 3) * STG_BYTES;
#pragma unroll
            for (int i = 0; i < 4; i++)
                cp_async16(pst + soff[i], gB + goff[i] + (ck + 3) * 64);
        }
        asm volatile("cp.async.commit_group;");
        stg_i = (stg_i + 1) & 3;
    }
    __syncthreads();   // all ldsm reads done before h overwrites stage region

    // ---- epilogue: h = clip((chi + clo/256)/16 + b1) -> smem f32 -------------
    float* hsm = (float*)(smem + SM_H);
    const float* b1s = (const float*)(smem + SM_B1);
    const float k1 = 1.f / 256.f, k2 = 1.f / 16.f;
#pragma unroll
    for (int mf = 0; mf < 4; mf++) {
#pragma unroll
        for (int nf = 0; nf < 4; nf++) {
            const int row0 = warpM * 64 + mf * 16 + (lane >> 2);
            const int col  = warpN * 32 + nf * 8 + 2 * (lane & 3);
            const float bb0 = b1s[col], bb1 = b1s[col + 1];
            float v0 = ((float)chi[mf][nf][0] + (float)clo[mf][nf][0] * k1) * k2 + bb0;
            float v1 = ((float)chi[mf][nf][1] + (float)clo[mf][nf][1] * k1) * k2 + bb1;
            float v2 = ((float)chi[mf][nf][2] + (float)clo[mf][nf][2] * k1) * k2 + bb0;
            float v3 = ((float)chi[mf][nf][3] + (float)clo[mf][nf][3] * k1) * k2 + bb1;
            v0 = fminf(fmaxf(v0, -1.f), 1.f);
            v1 = fminf(fmaxf(v1, -1.f), 1.f);
            v2 = fminf(fmaxf(v2, -1.f), 1.f);
            v3 = fminf(fmaxf(v3, -1.f), 1.f);
            *(float2*)&hsm[row0 * H_STRIDE + col]       = make_float2(v0, v1);
            *(float2*)&hsm[(row0 + 8) * H_STRIDE + col] = make_float2(v2, v3);
        }
    }
    __syncthreads();

    // ---- layer 2: partial[r][0..9] over this CTA's 256 cols ------------------
    {
        const int r  = tid >> 2;         // 0..127
        const int tg = tid & 3;          // 4 threads/row, 64 cols each
        const float* w2s = (const float*)(smem + SM_W2);
        float acc[10];
#pragma unroll
        for (int o = 0; o < 10; o++) acc[o] = 0.f;
#pragma unroll 4
        for (int j = 0; j < 64; j++) {
            const int cc = tg * 64 + ((j + tg * 8) & 63);
            const float hv = hsm[r * H_STRIDE + cc];
#pragma unroll
            for (int o = 0; o < 10; o++)
                acc[o] += hv * w2s[o * 256 + cc];
        }
#pragma unroll
        for (int o = 0; o < 10; o++) {
            acc[o] += __shfl_xor_sync(0xffffffffu, acc[o], 1);
            acc[o] += __shfl_xor_sync(0xffffffffu, acc[o], 2);
        }
        const size_t base = ((size_t)blockIdx.y * BATCH + m0 + r) * 16;
        if (tg == 0)
            *(float4*)&g_part[base]     = make_float4(acc[0], acc[1], acc[2], acc[3]);
        else if (tg == 1)
            *(float4*)&g_part[base + 4] = make_float4(acc[4], acc[5], acc[6], acc[7]);
        else if (tg == 2)
            *(float4*)&g_part[base + 8] = make_float4(acc[8], acc[9], 0.f, 0.f);
    }
}

// ---------------- launch -------------------------------------------------------
extern "C" void kernel_launch(void* const* d_in, const int* in_sizes, int n_in,
                              void* d_out, int out_size) {
    const float* x  = (const float*)d_in[0];
    const float* W1 = (const float*)d_in[1];
    const float* b1 = (const float*)d_in[2];
    const float* W2 = (const float*)d_in[3];
    const float* b2 = (const float*)d_in[4];
    float* out = (float*)d_out;

    cudaFuncSetAttribute(mlp_kernel,
                         cudaFuncAttributeMaxDynamicSharedMemorySize, SMEM_TOTAL);

    prep_x<<<(BATCH * KP + 255) / 256, 256>>>(x);
    prep_w<<<(HID * KP + 255) / 256, 256>>>(W1);
    mlp_kernel<<<dim3(NT_M, NT_N), 512, SMEM_TOTAL>>>(b1, W2);
    reduce_out<<<(BATCH * OUT_F + 255) / 256, 256>>>(b2, out);
}

// round 5
// speedup vs baseline: 1.0895x; 1.0895x over previous
#include <cuda_runtime.h>
#include <cuda_bf16.h>
#include <cstdint>
#include <cstddef>

// ============================================================================
// out = clip(x @ sign(W1)^T + b1, -1, 1) @ W2^T + b2
// sm_100 (no tcgen05): legacy bf16 mma.sync path, cp.async + ldmatrix.
// x split hi/lo bf16 (sign weights exact in bf16), both accumulate into the
// same f32 fragments. Layer 2 + final cross-tile reduction fused (atomic
// ticket, deterministic order). Exactly 2 kernel launches.
// ============================================================================

#define BATCH   8192
#define IN_F    784
#define HID     4096
#define OUT_F   10
#define KP      832            // 784 padded to 13*64
#define NCHUNK  13
#define TILE_M  128
#define TILE_N  256
#define NT_M    (BATCH / TILE_M)   // 64
#define NT_N    (HID / TILE_N)     // 16

// ---------------- device scratch ---------------------------------------------
#define AHI_OFF 0
#define ALO_OFF (BATCH * KP)
#define WB_OFF  (2 * BATCH * KP)
__device__ __nv_bfloat16 g_data[2 * BATCH * KP + HID * KP];
__device__ float g_part[(size_t)NT_N * BATCH * 16];
__device__ int   g_tick[NT_M];          // zero-init; reset by reducer each run

// ---------------- SMEM layout ------------------------------------------------
#define SM_B1    0                          // 256 f32
#define SM_W2    1024                       // 10*256 f32 = 10KB
#define SM_STG   12288                      // 3 stages x 64KB
#define STG_BYTES 65536
#define ST_AHI   0
#define ST_ALO   16384
#define ST_B     32768
#define SM_H     (SM_STG + STG_BYTES)       // h tile reuses stages 1+2
#define H_STRIDE 258                        // f32, pad for banks
#define SMEM_TOTAL (SM_H + TILE_M * H_STRIDE * 4)   // 209920
static_assert(SMEM_TOTAL <= 227 * 1024, "smem");

// ---------------- PTX helpers ------------------------------------------------
__device__ __forceinline__ uint32_t smem_u32(const void* p) {
    uint32_t a;
    asm("{ .reg .u64 t; cvta.to.shared.u64 t, %1; cvt.u32.u64 %0, t; }"
        : "=r"(a) : "l"(p));
    return a;
}
__device__ __forceinline__ void cp_async16(uint32_t sm, const void* gp) {
    asm volatile("cp.async.cg.shared.global [%0], [%1], 16;" :: "r"(sm), "l"(gp));
}
__device__ __forceinline__ void ldsm_x4(uint32_t& r0, uint32_t& r1,
                                        uint32_t& r2, uint32_t& r3, uint32_t a) {
    asm volatile("ldmatrix.sync.aligned.m8n8.x4.shared.b16 {%0,%1,%2,%3}, [%4];"
                 : "=r"(r0), "=r"(r1), "=r"(r2), "=r"(r3) : "r"(a));
}
__device__ __forceinline__ void mma_bf16(float& c0, float& c1, float& c2, float& c3,
                                         uint32_t a0, uint32_t a1, uint32_t a2,
                                         uint32_t a3, uint32_t b0, uint32_t b1) {
    asm volatile(
        "mma.sync.aligned.m16n8k16.row.col.f32.bf16.bf16.f32 "
        "{%0,%1,%2,%3}, {%4,%5,%6,%7}, {%8,%9}, {%0,%1,%2,%3};"
        : "+f"(c0), "+f"(c1), "+f"(c2), "+f"(c3)
        : "r"(a0), "r"(a1), "r"(a2), "r"(a3), "r"(b0), "r"(b1));
}

// ---------------- merged prep kernel -----------------------------------------
__global__ void prep(const float* __restrict__ x, const float* __restrict__ W1) {
    int idx = blockIdx.x * blockDim.x + threadIdx.x;
    if (idx < BATCH * KP) {
        int r = idx / KP, c = idx - r * KP;
        float v = (c < IN_F) ? x[r * IN_F + c] : 0.f;
        __nv_bfloat16 hi = __float2bfloat16(v);
        g_data[AHI_OFF + idx] = hi;
        g_data[ALO_OFF + idx] = __float2bfloat16(v - __bfloat162float(hi));
    } else {
        int i2 = idx - BATCH * KP;
        if (i2 >= HID * KP) return;
        int r = i2 / KP, c = i2 - r * KP;
        float s = 0.f;
        if (c < IN_F) {
            float v = W1[r * IN_F + c];
            s = (v > 0.f) ? 1.f : ((v < 0.f) ? -1.f : 0.f);
        }
        g_data[WB_OFF + i2] = __float2bfloat16(s);
    }
}

// ---------------- main fused kernel ------------------------------------------
__global__ void __launch_bounds__(512, 1)
mlp_kernel(const float* __restrict__ b1, const float* __restrict__ W2,
           const float* __restrict__ b2, float* __restrict__ out) {
    extern __shared__ __align__(128) char smem[];
    __shared__ int s_ticket;
    const uint32_t sb = smem_u32(smem);
    const int tid = threadIdx.x;
    const int lane = tid & 31, wid = tid >> 5;
    const int m0 = blockIdx.x * TILE_M;
    const int n0 = blockIdx.y * TILE_N;
    const int warpM = wid & 1;        // 2 along M
    const int warpN = wid >> 1;       // 8 along N

    // per-thread cp.async segment offsets (16B each; 8 per thread, 4096 total)
    uint32_t goff[8], soff[8];
#pragma unroll
    for (int i = 0; i < 8; i++) {
        int idx = tid + i * 512;
        int r, seg; uint32_t gb, sbs;
        if (idx < 1024)      { r = idx >> 3;              seg = idx & 7;
                               gb = (uint32_t)(AHI_OFF + (m0 + r) * KP) * 2; sbs = ST_AHI; }
        else if (idx < 2048) { int li = idx - 1024; r = li >> 3; seg = li & 7;
                               gb = (uint32_t)(ALO_OFF + (m0 + r) * KP) * 2; sbs = ST_ALO; }
        else                 { int li = idx - 2048; r = li >> 3; seg = li & 7;
                               gb = (uint32_t)(WB_OFF + (n0 + r) * KP) * 2;  sbs = ST_B; }
        goff[i] = gb + (uint32_t)(seg * 16);
        soff[i] = sbs + (uint32_t)(r * 128 + ((seg ^ (r & 7)) * 16));
    }
    const char* gB = (const char*)g_data;

    // prologue: stage 0 copies first (critical path), then b1/W2, then stages 1,2
    {
        uint32_t st = sb + SM_STG;
#pragma unroll
        for (int i = 0; i < 8; i++) cp_async16(st + soff[i], gB + goff[i]);
        asm volatile("cp.async.commit_group;");
    }
    if (tid < 256) ((float*)(smem + SM_B1))[tid] = b1[n0 + tid];
#pragma unroll
    for (int i = tid; i < 10 * 256; i += 512)
        ((float*)(smem + SM_W2))[i] = W2[(i >> 8) * HID + n0 + (i & 255)];
#pragma unroll
    for (int pc = 1; pc < 3; pc++) {
        uint32_t st = sb + SM_STG + pc * STG_BYTES;
#pragma unroll
        for (int i = 0; i < 8; i++)
            cp_async16(st + soff[i], gB + goff[i] + pc * 128);
        asm volatile("cp.async.commit_group;");
    }

    // ldmatrix per-thread invariants
    const int rA  = warpM * 64 + (lane & 15);
    const int sxA = rA & 7;
    const int kaA = lane >> 4;
    const int rB  = warpN * 32 + ((lane >> 4) << 3) + (lane & 7);
    const int sxB = rB & 7;
    const int kbB = (lane >> 3) & 1;

    float c[4][4][4];
#pragma unroll
    for (int mf = 0; mf < 4; mf++)
#pragma unroll
        for (int nf = 0; nf < 4; nf++)
#pragma unroll
            for (int q = 0; q < 4; q++) c[mf][nf][q] = 0.f;

    int stg_i = 0;
#pragma unroll 1
    for (int ck = 0; ck < NCHUNK; ck++) {
        asm volatile("cp.async.wait_group 2;");
        __syncthreads();
        const uint32_t stg = sb + SM_STG + stg_i * STG_BYTES;

#pragma unroll
        for (int ks = 0; ks < 4; ks++) {
            uint32_t b[4][2];
#pragma unroll
            for (int nfp = 0; nfp < 2; nfp++) {
                uint32_t addr = stg + ST_B + (uint32_t)(rB + nfp * 16) * 128
                              + (uint32_t)(((ks * 2 + kbB) ^ sxB) * 16);
                ldsm_x4(b[2 * nfp][0], b[2 * nfp][1],
                        b[2 * nfp + 1][0], b[2 * nfp + 1][1], addr);
            }
            uint32_t a[4][4];
#pragma unroll
            for (int mf = 0; mf < 4; mf++) {
                uint32_t addr = stg + ST_AHI + (uint32_t)(rA + mf * 16) * 128
                              + (uint32_t)(((ks * 2 + kaA) ^ sxA) * 16);
                ldsm_x4(a[mf][0], a[mf][1], a[mf][2], a[mf][3], addr);
            }
#pragma unroll
            for (int mf = 0; mf < 4; mf++)
#pragma unroll
                for (int nf = 0; nf < 4; nf++)
                    mma_bf16(c[mf][nf][0], c[mf][nf][1], c[mf][nf][2], c[mf][nf][3],
                             a[mf][0], a[mf][1], a[mf][2], a[mf][3],
                             b[nf][0], b[nf][1]);
            // lo half reuses B frags
#pragma unroll
            for (int mf = 0; mf < 4; mf++) {
                uint32_t addr = stg + ST_ALO + (uint32_t)(rA + mf * 16) * 128
                              + (uint32_t)(((ks * 2 + kaA) ^ sxA) * 16);
                ldsm_x4(a[mf][0], a[mf][1], a[mf][2], a[mf][3], addr);
            }
#pragma unroll
            for (int mf = 0; mf < 4; mf++)
#pragma unroll
                for (int nf = 0; nf < 4; nf++)
                    mma_bf16(c[mf][nf][0], c[mf][nf][1], c[mf][nf][2], c[mf][nf][3],
                             a[mf][0], a[mf][1], a[mf][2], a[mf][3],
                             b[nf][0], b[nf][1]);
        }

        __syncthreads();
        if (ck + 3 < NCHUNK) {
#pragma unroll
            for (int i = 0; i < 8; i++)
                cp_async16(stg + soff[i], gB + goff[i] + (ck + 3) * 128);
        }
        asm volatile("cp.async.commit_group;");
        stg_i++; if (stg_i == 3) stg_i = 0;
    }
    __syncthreads();

    // ---- epilogue: h = clip(C + b1) -> smem (f32) ---------------------------
    float* hsm = (float*)(smem + SM_H);
    const float* b1s = (const float*)(smem + SM_B1);
#pragma unroll
    for (int mf = 0; mf < 4; mf++) {
#pragma unroll
        for (int nf = 0; nf < 4; nf++) {
            const int row0 = warpM * 64 + mf * 16 + (lane >> 2);
            const int col  = warpN * 32 + nf * 8 + 2 * (lane & 3);
            const float bb0 = b1s[col], bb1 = b1s[col + 1];
            float v0 = fminf(fmaxf(c[mf][nf][0] + bb0, -1.f), 1.f);
            float v1 = fminf(fmaxf(c[mf][nf][1] + bb1, -1.f), 1.f);
            float v2 = fminf(fmaxf(c[mf][nf][2] + bb0, -1.f), 1.f);
            float v3 = fminf(fmaxf(c[mf][nf][3] + bb1, -1.f), 1.f);
            *(float2*)&hsm[row0 * H_STRIDE + col]       = make_float2(v0, v1);
            *(float2*)&hsm[(row0 + 8) * H_STRIDE + col] = make_float2(v2, v3);
        }
    }
    __syncthreads();

    // ---- layer 2: partial[r][0..9] over this CTA's 256 cols -----------------
    {
        const int r  = tid >> 2;         // 0..127
        const int tg = tid & 3;          // 4 threads/row, 64 cols each
        const float* w2s = (const float*)(smem + SM_W2);
        float acc[10];
#pragma unroll
        for (int o = 0; o < 10; o++) acc[o] = 0.f;
#pragma unroll 4
        for (int j = 0; j < 32; j++) {
            const int jj = (j + tg * 8) & 31;           // bank skew
            const int cc = tg * 64 + jj * 2;
            const float2 hv = *(const float2*)&hsm[r * H_STRIDE + cc];
#pragma unroll
            for (int o = 0; o < 10; o++) {
                const float2 wv = *(const float2*)&w2s[o * 256 + cc];
                acc[o] += hv.x * wv.x + hv.y * wv.y;
            }
        }
#pragma unroll
        for (int o = 0; o < 10; o++) {
            acc[o] += __shfl_xor_sync(0xffffffffu, acc[o], 1);
            acc[o] += __shfl_xor_sync(0xffffffffu, acc[o], 2);
        }
        const size_t base = ((size_t)blockIdx.y * BATCH + m0 + r) * 16;
        if (tg == 0)
            *(float4*)&g_part[base]     = make_float4(acc[0], acc[1], acc[2], acc[3]);
        else if (tg == 1)
            *(float4*)&g_part[base + 4] = make_float4(acc[4], acc[5], acc[6], acc[7]);
        else if (tg == 2)
            *(float4*)&g_part[base + 8] = make_float4(acc[8], acc[9], 0.f, 0.f);
    }

    // ---- last-arriving CTA for this M tile reduces all 16 N partials --------
    __threadfence();
    __syncthreads();
    if (tid == 0) s_ticket = atomicAdd(&g_tick[blockIdx.x], 1);
    __syncthreads();
    if (s_ticket == NT_N - 1) {
        __threadfence();   // acquire: all partials visible
        for (int i = tid; i < TILE_M * OUT_F; i += 512) {
            const int r = i / OUT_F, o = i - r * OUT_F;
            float acc = b2[o];
#pragma unroll
            for (int nt = 0; nt < NT_N; nt++)
                acc += g_part[((size_t)nt * BATCH + m0 + r) * 16 + o];
            out[(m0 + r) * OUT_F + o] = acc;
        }
        __syncthreads();
        if (tid == 0) atomicExch(&g_tick[blockIdx.x], 0);   // reset for next run
    }
}

// ---------------- launch -------------------------------------------------------
extern "C" void kernel_launch(void* const* d_in, const int* in_sizes, int n_in,
                              void* d_out, int out_size) {
    const float* x  = (const float*)d_in[0];
    const float* W1 = (const float*)d_in[1];
    const float* b1 = (const float*)d_in[2];
    const float* W2 = (const float*)d_in[3];
    const float* b2 = (const float*)d_in[4];
    float* out = (float*)d_out;

    cudaFuncSetAttribute(mlp_kernel,
                         cudaFuncAttributeMaxDynamicSharedMemorySize, SMEM_TOTAL);

    const int prep_elems = BATCH * KP + HID * KP;
    prep<<<(prep_elems + 255) / 256, 256>>>(x, W1);
    mlp_kernel<<<dim3(NT_M, NT_N), 512, SMEM_TOTAL>>>(b1, W2, b2, out);
}